// round 10
// baseline (speedup 1.0000x reference)
#include <cuda_runtime.h>

#define N_K_STEPS 512
#define N_STATE   128
#define N_INPUT   32
#define HIDDEN    256
#define FAN_IN    161   /* 1 + 128 + 32 */
#define NTHREADS  512
#define TRAJ      2

// Tsit5 tableau
__constant__ float c_C[6] = {0.0f, 0.161f, 0.327f, 0.9f, 0.9800255409045097f, 1.0f};
__constant__ float c_A[5][5] = {
  {0.161f, 0.f, 0.f, 0.f, 0.f},
  {-0.008480655492356989f, 0.335480655492357f, 0.f, 0.f, 0.f},
  {2.8971530571054935f, -6.359448489975075f, 4.3622954328695815f, 0.f, 0.f},
  {5.325864828439257f, -11.748883564062828f, 7.4955393428898365f, -0.09249506636175525f, 0.f},
  {5.86145544294642f, -12.92096931784711f, 8.159367898576159f, -0.071584973281401f, -0.028269050394068383f}
};
__constant__ float c_B[6] = {0.09646076681806523f, 0.01f, 0.4798896504144996f,
                             1.379008574103742f, -3.290069515436081f, 2.324710524099774f};

struct SmemLayout {
  float4 w2q[64 * 128];        // W2 quads [k-quad q][output o] = W2[o][4q..4q+3]  (128 KB)
  float4 zs4[TRAJ][42];        // per-traj z, padded to 168 floats ([161..167]=0)
  float  hs[TRAJ][HIDDEN];     // per-traj hidden activations
  float  ksh[TRAJ][5][128];    // per-traj k1..k5 (owner-thread private)
  float  ustg[TRAJ][6][32];    // per-traj interpolated u per stage ([0] unused)
  float  tsh[N_K_STEPS];       // ts cached in smem
};

__device__ __forceinline__ float2 ffma2f(float2 a, float2 b, float2 c) {
  union { float2 f; unsigned long long u; } ua, ub, uc;
  ua.f = a; ub.f = b; uc.f = c;
  asm("fma.rn.f32x2 %0, %1, %2, %0;" : "+l"(uc.u) : "l"(ua.u), "l"(ub.u));
  return uc.f;
}

__device__ __forceinline__ float fast_tanh(float x) {
  // tanh(x) = sign(x)*(1 - 2/(1+e^{2|x|})) via ex2/rcp approx (~1e-6 abs err)
  float ax = fabsf(x);
  float e;
  asm("ex2.approx.f32 %0, %1;" : "=f"(e) : "f"(ax * 2.885390081777927f)); // 2|x|*log2(e)
  float r;
  asm("rcp.approx.f32 %0, %1;" : "=f"(r) : "f"(e + 1.0f));
  float t = fmaf(-2.0f, r, 1.0f);
  return copysignf(t, x);
}

__global__ __launch_bounds__(NTHREADS, 1)
void ode_tsit5_kernel(const float* __restrict__ ts, const float* __restrict__ y0,
                      const float* __restrict__ us, const float* __restrict__ W1,
                      const float* __restrict__ b1, const float* __restrict__ W2,
                      const float* __restrict__ b2, float* __restrict__ out,
                      int n_steps)
{
  extern __shared__ SmemLayout smem_raw[];
  SmemLayout& S = smem_raw[0];
  const int tid  = threadIdx.x;
  const int lane = tid & 31;
  const int wrp  = tid >> 5;
  const int b0   = blockIdx.x * TRAJ;

  const float* usb0 = us + (size_t)b0 * N_K_STEPS * N_INPUT;
  const float* usb1 = usb0 + (size_t)N_K_STEPS * N_INPUT;
  float* outb0 = out + (size_t)b0 * N_K_STEPS * N_STATE;
  float* outb1 = outb0 + (size_t)N_K_STEPS * N_STATE;

  // ---- stage-B role: 2 threads per hidden unit (lanes L / L+16 of one warp)
  const int u    = (wrp << 4) | (lane & 15);   // hidden unit 0..255
  const int half = lane >> 4;                  // 0: z[0:84), 1: z[84:168)
  const int zb   = half * 21;                  // float4 base into zs4[tr]

  // ---- stage-C role: 4 threads per output, all in one warp (xor 8 / xor 16)
  const int o  = (wrp << 3) | (lane & 7);      // output 0..127
  const int sl = lane >> 3;                    // k-slice 0..3
  const int qb = sl * 16;                      // quad base

  // ---- one-time: W2 -> shared as float4 [k-quad][output]
  for (int idx = tid; idx < 64 * 128; idx += NTHREADS) {
    int q = idx >> 7, oo = idx & 127;
    const float* src = W2 + oo * HIDDEN + 4 * q;
    S.w2q[idx] = make_float4(src[0], src[1], src[2], src[3]);
  }
  // ---- one-time: ts -> shared
  for (int i = tid; i < n_steps; i += NTHREADS) S.tsh[i] = ts[i];

  // ---- one-time: W1 half-row -> 21 float4 regs (84 regs)
  float4 w1r[21];
  {
    const float* w1row = W1 + u * FAN_IN;
    #pragma unroll
    for (int j = 0; j < 21; ++j) {
      float v[4];
      #pragma unroll
      for (int c = 0; c < 4; ++c) {
        int f = half * 84 + 4 * j + c;
        v[c] = (f < FAN_IN) ? w1row[f] : 0.0f;
      }
      w1r[j] = make_float4(v[0], v[1], v[2], v[3]);
    }
  }
  const float b1t = b1[u];
  const float b2t = b2[o];

  float* z0f = (float*)S.zs4[0];
  float* z1f = (float*)S.zs4[1];

  float y0r = 0.0f, y1r = 0.0f;   // only meaningful on sl==0 owner threads
  if (sl == 0) {
    y0r = y0[b0 * N_STATE + o];
    y1r = y0[(b0 + 1) * N_STATE + o];
    outb0[o] = y0r;  z0f[1 + o] = y0r;
    outb1[o] = y1r;  z1f[1 + o] = y1r;
  }
  if (tid < 8)       z0f[160 + tid] = 0.0f;      // pads ([160] overwritten by t)
  else if (tid < 16) z1f[160 + (tid - 8)] = 0.0f;
  if (sl == 1 && o < 32)              z0f[129 + o]        = usb0[o];
  if (sl == 1 && o >= 32 && o < 64)   z1f[129 + (o - 32)] = usb1[o - 32];
  if (sl == 2 && o == 0) z0f[0] = ts[0];
  if (sl == 2 && o == 1) z1f[0] = ts[0];
  __syncthreads();

  const float4* hs0 = (const float4*)S.hs[0];
  const float4* hs1 = (const float4*)S.hs[1];

  for (int s = 0; s < n_steps - 1; ++s) {
    const float t0 = S.tsh[s];
    const float hstep = S.tsh[s + 1] - t0;

    // ---- step setup: Hermite-interpolated u for stages 1..5, both trajectories
    if (tid < 320) {
      const int tr  = (tid >= 160);
      const int r   = tr ? (tid - 160) : tid;
      const int stg = (r >> 5) + 1;    // 1..5
      const int m   = r & 31;
      const float* usb = tr ? usb1 : usb0;
      float u0v = usb[s * N_INPUT + m];
      float u1v = usb[(s + 1) * N_INPUT + m];
      float hd1 = u1v - u0v;           // h*d[s+1] == u1-u0 exactly
      float hd0;
      if (s == 0) {
        hd0 = hd1;
      } else {
        float um  = usb[(s - 1) * N_INPUT + m];
        float dtp = t0 - S.tsh[s - 1];
        hd0 = hstep * (u0v - um) / dtp;
      }
      float th = c_C[stg];
      float t2 = th * th, t3 = t2 * th;
      S.ustg[tr][stg][m] = (2.f*t3 - 3.f*t2 + 1.f) * u0v + (t3 - 2.f*t2 + th) * hd0
                         + (-2.f*t3 + 3.f*t2) * u1v + (t3 - t2) * hd1;
    }

    #pragma unroll 1
    for (int st = 0; st < 6; ++st) {
      __syncthreads();   // bar1: z (both trajectories) ready for stage st

      // ---- (B) hidden half-dots for both trajectories (4 indep FFMA2 chains)
      {
        float2 p00 = make_float2(0.f, 0.f), p01 = p00, p10 = p00, p11 = p00;
        #pragma unroll
        for (int j = 0; j < 21; ++j) {
          float4 wv = w1r[j];
          float4 zv = S.zs4[0][zb + j];
          float4 zw = S.zs4[1][zb + j];
          p00 = ffma2f(make_float2(wv.x, wv.y), make_float2(zv.x, zv.y), p00);
          p01 = ffma2f(make_float2(wv.z, wv.w), make_float2(zv.z, zv.w), p01);
          p10 = ffma2f(make_float2(wv.x, wv.y), make_float2(zw.x, zw.y), p10);
          p11 = ffma2f(make_float2(wv.z, wv.w), make_float2(zw.z, zw.w), p11);
        }
        float s0 = (p00.x + p00.y) + (p01.x + p01.y);
        float s1 = (p10.x + p10.y) + (p11.x + p11.y);
        s0 += __shfl_xor_sync(0xffffffffu, s0, 16);
        s1 += __shfl_xor_sync(0xffffffffu, s1, 16);
        if (half == 0) {
          S.hs[0][u] = fast_tanh(s0 + b1t);
          S.hs[1][u] = fast_tanh(s1 + b1t);
        }
      }
      __syncthreads();   // bar2: h ready

      // ---- (C) output quarter-dots: one w2 load feeds BOTH trajectories
      {
        float2 c00 = make_float2(0.f, 0.f), c01 = c00, c10 = c00, c11 = c00;
        #pragma unroll
        for (int j = 0; j < 16; ++j) {
          float4 wv = S.w2q[(qb + j) * 128 + o];
          float4 h0 = hs0[qb + j];
          float4 h1 = hs1[qb + j];
          c00 = ffma2f(make_float2(wv.x, wv.y), make_float2(h0.x, h0.y), c00);
          c01 = ffma2f(make_float2(wv.z, wv.w), make_float2(h0.z, h0.w), c01);
          c10 = ffma2f(make_float2(wv.x, wv.y), make_float2(h1.x, h1.y), c10);
          c11 = ffma2f(make_float2(wv.z, wv.w), make_float2(h1.z, h1.w), c11);
        }
        float k0 = (c00.x + c00.y) + (c01.x + c01.y);
        float k1 = (c10.x + c10.y) + (c11.x + c11.y);
        k0 += __shfl_xor_sync(0xffffffffu, k0, 8);
        k0 += __shfl_xor_sync(0xffffffffu, k0, 16);
        k1 += __shfl_xor_sync(0xffffffffu, k1, 8);
        k1 += __shfl_xor_sync(0xffffffffu, k1, 16);
        k0 += b2t;  k1 += b2t;

        if (st < 5) {
          if (sl == 0) {
            // owner-thread-private k storage (same thread reads later, no sync)
            S.ksh[0][st][o] = k0;
            S.ksh[1][st][o] = k1;
            float a0 = c_A[st][st] * k0;
            float a1 = c_A[st][st] * k1;
            for (int j = 0; j < st; ++j) {
              a0 += c_A[st][j] * S.ksh[0][j][o];
              a1 += c_A[st][j] * S.ksh[1][j][o];
            }
            z0f[1 + o] = y0r + hstep * a0;
            z1f[1 + o] = y1r + hstep * a1;
          } else {
            if (sl == 1 && o < 32)            z0f[129 + o]        = S.ustg[0][st + 1][o];
            if (sl == 1 && o >= 32 && o < 64) z1f[129 + (o - 32)] = S.ustg[1][st + 1][o - 32];
            if (sl == 2 && o == 0) z0f[0] = t0 + c_C[st + 1] * hstep;
            if (sl == 2 && o == 1) z1f[0] = t0 + c_C[st + 1] * hstep;
          }
        } else {
          if (sl == 0) {
            float a0 = c_B[5] * k0;
            float a1 = c_B[5] * k1;
            #pragma unroll
            for (int j = 0; j < 5; ++j) {
              a0 += c_B[j] * S.ksh[0][j][o];
              a1 += c_B[j] * S.ksh[1][j][o];
            }
            y0r += hstep * a0;
            y1r += hstep * a1;
            outb0[(size_t)(s + 1) * N_STATE + o] = y0r;
            outb1[(size_t)(s + 1) * N_STATE + o] = y1r;
            z0f[1 + o] = y0r;                  // z for next step's stage 0
            z1f[1 + o] = y1r;
          } else {
            if (sl == 1 && o < 32)            z0f[129 + o]        = usb0[(s + 1) * N_INPUT + o];
            if (sl == 1 && o >= 32 && o < 64) z1f[129 + (o - 32)] = usb1[(s + 1) * N_INPUT + (o - 32)];
            if (sl == 2 && o == 0) z0f[0] = S.tsh[s + 1];
            if (sl == 2 && o == 1) z1f[0] = S.tsh[s + 1];
          }
        }
      }
    }
  }
}

extern "C" void kernel_launch(void* const* d_in, const int* in_sizes, int n_in,
                              void* d_out, int out_size) {
  const float* ts = (const float*)d_in[0];
  const float* y0 = (const float*)d_in[1];
  const float* us = (const float*)d_in[2];
  const float* W1 = (const float*)d_in[3];
  const float* b1 = (const float*)d_in[4];
  const float* W2 = (const float*)d_in[5];
  const float* b2 = (const float*)d_in[6];
  float* out = (float*)d_out;

  const int n_steps = in_sizes[0];             // 512
  const int batch   = in_sizes[1] / N_STATE;   // 64

  const size_t smem_bytes = sizeof(SmemLayout);
  cudaFuncSetAttribute(ode_tsit5_kernel,
                       cudaFuncAttributeMaxDynamicSharedMemorySize, (int)smem_bytes);
  ode_tsit5_kernel<<<batch / TRAJ, NTHREADS, smem_bytes>>>(ts, y0, us, W1, b1, W2, b2, out, n_steps);
}

// round 13
// speedup vs baseline: 1.8838x; 1.8838x over previous
#include <cuda_runtime.h>
#include <cstdint>

#define N_K_STEPS 512
#define N_STATE   128
#define N_INPUT   32
#define HIDDEN    256
#define FAN_IN    161   /* 1 + 128 + 32 */
#define NTH       256

// Tsit5 tableau
__constant__ float c_C[6] = {0.0f, 0.161f, 0.327f, 0.9f, 0.9800255409045097f, 1.0f};
__constant__ float c_A[5][5] = {
  {0.161f, 0.f, 0.f, 0.f, 0.f},
  {-0.008480655492356989f, 0.335480655492357f, 0.f, 0.f, 0.f},
  {2.8971530571054935f, -6.359448489975075f, 4.3622954328695815f, 0.f, 0.f},
  {5.325864828439257f, -11.748883564062828f, 7.4955393428898365f, -0.09249506636175525f, 0.f},
  {5.86145544294642f, -12.92096931784711f, 8.159367898576159f, -0.071584973281401f, -0.028269050394068383f}
};
__constant__ float c_B[6] = {0.09646076681806523f, 0.01f, 0.4798896504144996f,
                             1.379008574103742f, -3.290069515436081f, 2.324710524099774f};

// ---- dynamic smem offsets ----
#define OFF_W2   0        /* 32 k-quads x 128 outputs float4 = 64 KB */
#define OFF_Z    65536    /* z: 168 floats (pad to 704 B)            */
#define OFF_H    66304    /* local h: 128 floats                     */
#define OFF_KSH  66816    /* k1..k5: 5 x 128 floats                  */
#define OFF_RECV 69376    /* peer partials: 2 x 128 floats           */
#define OFF_USTG 70400    /* 6 x 32 floats                           */
#define OFF_TSH  71168    /* ts cache: 512 floats                    */
#define OFF_MBAR 73216    /* 2 mbarriers (16 B)                      */
#define SMEM_TOTAL 73280

__device__ __forceinline__ uint32_t smem_u32(const void* p) {
  uint32_t a;
  asm("{ .reg .u64 t; cvta.to.shared.u64 t, %1; cvt.u32.u64 %0, t; }" : "=r"(a) : "l"(p));
  return a;
}

__device__ __forceinline__ uint32_t mapa_peer(uint32_t laddr, uint32_t prank) {
  uint32_t r;
  asm("mapa.shared::cluster.u32 %0, %1, %2;" : "=r"(r) : "r"(laddr), "r"(prank));
  return r;
}

__device__ __forceinline__ void dsmem_st_f32(uint32_t raddr, float v) {
  asm volatile("st.shared::cluster.f32 [%0], %1;" :: "r"(raddr), "f"(v) : "memory");
}

__device__ __forceinline__ void mbar_arrive_remote(uint32_t raddr) {
  // release orders THIS thread's prior DSMEM store before the arrive
  asm volatile("mbarrier.arrive.release.cluster.shared::cluster.b64 _, [%0];"
               :: "r"(raddr) : "memory");
}

__device__ __forceinline__ void mbar_wait_cluster(uint32_t addr, uint32_t parity) {
  uint32_t done;
  asm volatile(
    "{\n\t.reg .pred p;\n\t"
    "mbarrier.try_wait.parity.acquire.cluster.shared::cta.b64 p, [%1], %2;\n\t"
    "selp.b32 %0, 1, 0, p;\n\t}"
    : "=r"(done) : "r"(addr), "r"(parity) : "memory");
  while (!done) {
    asm volatile(
      "{\n\t.reg .pred p;\n\t"
      "mbarrier.try_wait.parity.acquire.cluster.shared::cta.b64 p, [%1], %2, 0x989680;\n\t"
      "selp.b32 %0, 1, 0, p;\n\t}"
      : "=r"(done) : "r"(addr), "r"(parity) : "memory");
  }
}

__device__ __forceinline__ float2 ffma2f(float2 a, float2 b, float2 c) {
  union { float2 f; unsigned long long u; } ua, ub, uc;
  ua.f = a; ub.f = b; uc.f = c;
  asm("fma.rn.f32x2 %0, %1, %2, %0;" : "+l"(uc.u) : "l"(ua.u), "l"(ub.u));
  return uc.f;
}

__device__ __forceinline__ float fast_tanh(float x) {
  float ax = fabsf(x);
  float e;
  asm("ex2.approx.f32 %0, %1;" : "=f"(e) : "f"(ax * 2.885390081777927f));
  float r;
  asm("rcp.approx.f32 %0, %1;" : "=f"(r) : "f"(e + 1.0f));
  float t = fmaf(-2.0f, r, 1.0f);
  return copysignf(t, x);
}

__global__ __launch_bounds__(NTH, 1) __cluster_dims__(2, 1, 1)
void ode_tsit5_kernel(const float* __restrict__ ts, const float* __restrict__ y0,
                      const float* __restrict__ us, const float* __restrict__ W1,
                      const float* __restrict__ b1, const float* __restrict__ W2,
                      const float* __restrict__ b2, float* __restrict__ out,
                      int n_steps)
{
  extern __shared__ char smem[];
  const uint32_t sb = smem_u32(smem);
  const int tid  = threadIdx.x;
  const int lane = tid & 31;
  const int wrp  = tid >> 5;
  uint32_t rank;
  asm("mov.u32 %0, %%cluster_ctarank;" : "=r"(rank));
  const int traj = blockIdx.x >> 1;

  const float* usb = us + (size_t)traj * N_K_STEPS * N_INPUT;
  float* outb = out + (size_t)traj * N_K_STEPS * N_STATE;

  // unified role: o == local hidden unit == output index, 2 threads each
  const int o    = (wrp << 4) | (lane & 15);   // 0..127
  const int half = lane >> 4;                  // B: z-half ; C: k-half
  const int zb   = half * 21;

  float4* w2q = (float4*)(smem + OFF_W2);
  float*  zsf = (float*)(smem + OFF_Z);
  float4* zs4 = (float4*)(smem + OFF_Z);
  float*  hs  = (float*)(smem + OFF_H);
  const float4* hs4 = (const float4*)(smem + OFF_H);
  float*  ksh = (float*)(smem + OFF_KSH);
  float*  rcv = (float*)(smem + OFF_RECV);
  float*  ustg= (float*)(smem + OFF_USTG);
  float*  tsh = (float*)(smem + OFF_TSH);

  // ---- one-time: this CTA's W2 column-half -> smem float4 [k-quad][o]
  for (int idx = tid; idx < 32 * 128; idx += NTH) {
    int q = idx >> 7, oo = idx & 127;
    const float* src = W2 + oo * HIDDEN + rank * 128 + 4 * q;
    w2q[idx] = make_float4(src[0], src[1], src[2], src[3]);
  }
  for (int i = tid; i < n_steps; i += NTH) tsh[i] = ts[i];

  // ---- one-time: W1 half-row of unit (rank*128 + o) -> 21 float4 regs
  float4 w1r[21];
  {
    const float* w1row = W1 + (rank * 128 + o) * FAN_IN;
    #pragma unroll
    for (int j = 0; j < 21; ++j) {
      float v[4];
      #pragma unroll
      for (int c = 0; c < 4; ++c) {
        int f = half * 84 + 4 * j + c;
        v[c] = (f < FAN_IN) ? w1row[f] : 0.0f;
      }
      w1r[j] = make_float4(v[0], v[1], v[2], v[3]);
    }
  }
  const float b1t = b1[rank * 128 + o];
  const float b2t = b2[o];

  float y = 0.0f;
  if (half == 0) {
    y = y0[traj * N_STATE + o];
    if (rank == 0) outb[o] = y;        // out row 0 = y0
    zsf[1 + o] = y;
  }
  if (tid < 7) zsf[161 + tid] = 0.0f;  // z pad
  if (half == 1) {
    if (wrp < 2)                           zsf[129 + (wrp * 16 + (lane & 15))] = usb[wrp * 16 + (lane & 15)];
    else if (wrp == 2 && (lane & 15) == 0) zsf[0] = ts[0];
  }

  if (tid == 0) {
    // count = 128: one arrive per storing thread (per-thread release covers each store)
    asm volatile("mbarrier.init.shared.b64 [%0], %1;" :: "r"(sb + OFF_MBAR),     "r"(128u) : "memory");
    asm volatile("mbarrier.init.shared.b64 [%0], %1;" :: "r"(sb + OFF_MBAR + 8), "r"(128u) : "memory");
  }
  const uint32_t prank = rank ^ 1u;
  const uint32_t peer_recv = mapa_peer(sb + OFF_RECV, prank);
  const uint32_t peer_mbar = mapa_peer(sb + OFF_MBAR, prank);
  __syncthreads();
  asm volatile("barrier.cluster.arrive.aligned;" ::: "memory");
  asm volatile("barrier.cluster.wait.aligned;" ::: "memory");

  unsigned e = 0;   // eval counter: buffer = e&1, phase = (e>>1)&1

  for (int s = 0; s < n_steps - 1; ++s) {
    const float t0 = tsh[s];
    const float hstep = tsh[s + 1] - t0;

    // ---- Hermite-interpolated u for stages 1..5 (read >=2 barriers later)
    if (tid < 160) {
      int stg = (tid >> 5) + 1;
      int m   = tid & 31;
      float u0v = usb[s * N_INPUT + m];
      float u1v = usb[(s + 1) * N_INPUT + m];
      float hd1 = u1v - u0v;
      float hd0;
      if (s == 0) {
        hd0 = hd1;
      } else {
        float um  = usb[(s - 1) * N_INPUT + m];
        float dtp = t0 - tsh[s - 1];
        hd0 = hstep * (u0v - um) / dtp;
      }
      float th = c_C[stg];
      float t2 = th * th, t3 = t2 * th;
      ustg[stg * 32 + m] = (2.f*t3 - 3.f*t2 + 1.f) * u0v + (t3 - 2.f*t2 + th) * hd0
                         + (-2.f*t3 + 3.f*t2) * u1v + (t3 - t2) * hd1;
    }

    #pragma unroll 1
    for (int st = 0; st < 6; ++st) {
      __syncthreads();   // bar1: z ready

      // ---- (B) hidden half-dot for local unit + shfl + tanh
      {
        float2 a0 = make_float2(0.f, 0.f), a1 = a0;
        #pragma unroll
        for (int j = 0; j < 21; ++j) {
          float4 zv = zs4[zb + j];
          float4 wv = w1r[j];
          a0 = ffma2f(make_float2(wv.x, wv.y), make_float2(zv.x, zv.y), a0);
          a1 = ffma2f(make_float2(wv.z, wv.w), make_float2(zv.z, zv.w), a1);
        }
        float sum = (a0.x + a0.y) + (a1.x + a1.y);
        sum += __shfl_xor_sync(0xffffffffu, sum, 16);
        if (half == 0) hs[o] = fast_tanh(sum + b1t);
      }
      __syncthreads();   // bar2: h ready

      // ---- (C) local k-partial over this CTA's 128 hidden units
      float kpart;
      {
        float2 c0 = make_float2(0.f, 0.f), c1 = c0;
        #pragma unroll
        for (int j = 0; j < 16; j += 2) {
          float4 hv = hs4[half * 16 + j];
          float4 wv = w2q[(half * 16 + j) * 128 + o];
          c0 = ffma2f(make_float2(wv.x, wv.y), make_float2(hv.x, hv.y), c0);
          c1 = ffma2f(make_float2(wv.z, wv.w), make_float2(hv.z, hv.w), c1);
          float4 hw = hs4[half * 16 + j + 1];
          float4 ww = w2q[(half * 16 + j + 1) * 128 + o];
          c0 = ffma2f(make_float2(ww.x, ww.y), make_float2(hw.x, hw.y), c0);
          c1 = ffma2f(make_float2(ww.z, ww.w), make_float2(hw.z, hw.w), c1);
        }
        kpart = (c0.x + c0.y) + (c1.x + c1.y);
        kpart += __shfl_xor_sync(0xffffffffu, kpart, 16);
      }

      // ---- exchange: each owner stores its partial to peer then arrives (release)
      if (half == 0) {
        dsmem_st_f32(peer_recv + (e & 1u) * 512u + (uint32_t)o * 4u, kpart);
        mbar_arrive_remote(peer_mbar + (e & 1u) * 8u);
      } else {
        // idle half writes u/t parts of next z meanwhile
        if (wrp < 2) {
          int uidx = wrp * 16 + (lane & 15);
          zsf[129 + uidx] = (st < 5) ? ustg[(st + 1) * 32 + uidx]
                                     : usb[(s + 1) * N_INPUT + uidx];
        } else if (wrp == 2 && (lane & 15) == 0) {
          zsf[0] = (st < 5) ? (t0 + c_C[st + 1] * hstep) : tsh[s + 1];
        }
      }

      // ---- owners: wait for all 128 peer partials (acquire), fold, write z y-part
      if (half == 0) {
        mbar_wait_cluster(sb + OFF_MBAR + (e & 1u) * 8u, (e >> 1) & 1u);
        float kv = kpart + rcv[(e & 1u) * 128 + o] + b2t;
        if (st < 5) {
          ksh[st * 128 + o] = kv;
          float acc = c_A[st][st] * kv;
          for (int j = 0; j < st; ++j) acc += c_A[st][j] * ksh[j * 128 + o];
          zsf[1 + o] = y + hstep * acc;
        } else {
          float acc = c_B[5] * kv;
          #pragma unroll
          for (int j = 0; j < 5; ++j) acc += c_B[j] * ksh[j * 128 + o];
          y += hstep * acc;
          if (rank == 0) outb[(size_t)(s + 1) * N_STATE + o] = y;
          zsf[1 + o] = y;
        }
      }
      ++e;
    }
  }

  asm volatile("barrier.cluster.arrive.aligned;" ::: "memory");
  asm volatile("barrier.cluster.wait.aligned;" ::: "memory");
}

extern "C" void kernel_launch(void* const* d_in, const int* in_sizes, int n_in,
                              void* d_out, int out_size) {
  const float* ts = (const float*)d_in[0];
  const float* y0 = (const float*)d_in[1];
  const float* us = (const float*)d_in[2];
  const float* W1 = (const float*)d_in[3];
  const float* b1 = (const float*)d_in[4];
  const float* W2 = (const float*)d_in[5];
  const float* b2 = (const float*)d_in[6];
  float* out = (float*)d_out;

  const int n_steps = in_sizes[0];             // 512
  const int batch   = in_sizes[1] / N_STATE;   // 64

  cudaFuncSetAttribute(ode_tsit5_kernel,
                       cudaFuncAttributeMaxDynamicSharedMemorySize, SMEM_TOTAL);
  ode_tsit5_kernel<<<batch * 2, NTH, SMEM_TOTAL>>>(ts, y0, us, W1, b1, W2, b2, out, n_steps);
}